// round 2
// baseline (speedup 1.0000x reference)
#include <cuda_runtime.h>
#include <math.h>

// ---------------------------------------------------------------------------
// GCN forward, restructured:
//   t1 = A x                (aggregate 64-dim)           [CSR, no float atomics]
//   h  = elu(t1 @ W1 + b1)  (GEMM 100k x 64 x 128)
//   t2 = A h  --> pooled_g += t2 rows (fused, atomic into 64x128)
//   pooled_mean @ W2 + b2 -> concat stats -> MLP -> log_softmax   (tiny, 1 kernel)
// A = D^-1/2 (Adj + I) D^-1/2, applied as: dinv[dst]*(sum dinv[src]*v[src]) + dinv[i]^2*v[i]
// NOTE: harness delivers integer inputs as int32 (edge_index, batch).
// ---------------------------------------------------------------------------

#define MAXN 100000
#define MAXE 1600000
#define MAXG 64

__device__ int   g_indeg[MAXN];
__device__ int   g_rowptr[MAXN + 1];
__device__ int   g_cursor[MAXN];
__device__ int   g_col[MAXE];
__device__ float g_dinv[MAXN];
__device__ __align__(16) float g_t1[(size_t)MAXN * 64];
__device__ __align__(16) float g_h[(size_t)MAXN * 128];
__device__ float g_pooled[MAXG * 128];
__device__ float g_cnt[MAXG];

// ---------------- init scratch (must run every graph replay) ----------------
__global__ void init_kernel(int n, int g) {
    int i = blockIdx.x * blockDim.x + threadIdx.x;
    if (i < n) g_indeg[i] = 0;
    if (i < g * 128) g_pooled[i] = 0.0f;
    if (i < g) g_cnt[i] = 0.0f;
}

// ---------------- count in-degree (real edges only) --------------------------
__global__ void count_kernel(const int* __restrict__ ei, int e) {
    int idx = blockIdx.x * blockDim.x + threadIdx.x;
    if (idx < e) {
        int d = ei[e + idx];
        atomicAdd(&g_indeg[d], 1);
    }
}

// ---------------- single-block exclusive scan -> rowptr ----------------------
__global__ void __launch_bounds__(1024) scan_kernel(int n) {
    __shared__ int warp_sums[32];
    __shared__ int carry_s;
    int tid = threadIdx.x;
    int lane = tid & 31, wid = tid >> 5;
    if (tid == 0) carry_s = 0;
    __syncthreads();
    const int TILE = 1024 * 8;
    for (int base = 0; base < n; base += TILE) {
        int v[8];
        int s = 0;
        int i0 = base + tid * 8;
#pragma unroll
        for (int j = 0; j < 8; j++) {
            int i = i0 + j;
            int x = (i < n) ? g_indeg[i] : 0;
            v[j] = x; s += x;
        }
        int inc = s;
#pragma unroll
        for (int off = 1; off < 32; off <<= 1) {
            int t = __shfl_up_sync(0xffffffffu, inc, off);
            if (lane >= off) inc += t;
        }
        if (lane == 31) warp_sums[wid] = inc;
        __syncthreads();
        if (wid == 0) {
            int winc = warp_sums[lane];
#pragma unroll
            for (int off = 1; off < 32; off <<= 1) {
                int t = __shfl_up_sync(0xffffffffu, winc, off);
                if (lane >= off) winc += t;
            }
            warp_sums[lane] = winc;
        }
        __syncthreads();
        int carry = carry_s;
        int warp_excl = (wid > 0) ? warp_sums[wid - 1] : 0;
        int run = carry + warp_excl + (inc - s);
#pragma unroll
        for (int j = 0; j < 8; j++) {
            int i = i0 + j;
            if (i < n) g_rowptr[i] = run;
            run += v[j];
        }
        __syncthreads();
        if (tid == 0) carry_s = carry + warp_sums[31];
        __syncthreads();
    }
    if (tid == 0) g_rowptr[n] = carry_s;
}

// ---------------- dinv + cursor ----------------------------------------------
__global__ void dinv_cursor_kernel(int n) {
    int i = blockIdx.x * blockDim.x + threadIdx.x;
    if (i < n) {
        g_dinv[i] = rsqrtf((float)(g_indeg[i] + 1));
        g_cursor[i] = g_rowptr[i];
    }
}

// ---------------- scatter edges into CSR --------------------------------------
__global__ void scatter_kernel(const int* __restrict__ ei, int e) {
    int idx = blockIdx.x * blockDim.x + threadIdx.x;
    if (idx < e) {
        int s = ei[idx];
        int d = ei[e + idx];
        int pos = atomicAdd(&g_cursor[d], 1);
        g_col[pos] = s;
    }
}

// ---------------- agg1: t1 = A x  (64 features, warp per node) ----------------
__global__ void agg1_kernel(const float* __restrict__ x, int n) {
    int warp = (blockIdx.x * blockDim.x + threadIdx.x) >> 5;
    int lane = threadIdx.x & 31;
    if (warp >= n) return;
    int i = warp;
    int p0 = g_rowptr[i], p1 = g_rowptr[i + 1];
    float2 acc = make_float2(0.f, 0.f);
    for (int p = p0; p < p1; ++p) {
        int s = g_col[p];
        float w = g_dinv[s];
        float2 v = *(const float2*)(x + (size_t)s * 64 + lane * 2);
        acc.x = fmaf(w, v.x, acc.x);
        acc.y = fmaf(w, v.y, acc.y);
    }
    float di = g_dinv[i];
    float2 xi = *(const float2*)(x + (size_t)i * 64 + lane * 2);
    float2 r;
    r.x = di * acc.x + di * di * xi.x;
    r.y = di * acc.y + di * di * xi.y;
    *(float2*)(g_t1 + (size_t)i * 64 + lane * 2) = r;
}

// ---------------- GEMM: h = elu(t1 @ W1 + b1)  (64 rows / block) --------------
__global__ void __launch_bounds__(256) gemm1_kernel(const float* __restrict__ W1,
                                                    const float* __restrict__ b1,
                                                    int n) {
    __shared__ float As[64 * 64];
    __shared__ float Ws[64 * 128];
    int tid = threadIdx.x;
    int base = blockIdx.x * 64;

    const float4* Wv = (const float4*)W1;
    float4* Wsv = (float4*)Ws;
#pragma unroll
    for (int i = 0; i < 8; i++) Wsv[tid + i * 256] = Wv[tid + i * 256];

    const float4* Av = (const float4*)(g_t1 + (size_t)base * 64);
    float4* Asv = (float4*)As;
#pragma unroll
    for (int i = 0; i < 4; i++) {
        int idx = tid + i * 256;
        int row = base + (idx >> 4);
        float4 v = (row < n) ? Av[idx] : make_float4(0.f, 0.f, 0.f, 0.f);
        Asv[idx] = v;
    }
    __syncthreads();

    int tx = tid & 31, ty = tid >> 5;
    int c0 = tx * 4, r0 = ty * 8;
    float acc[8][4];
#pragma unroll
    for (int r = 0; r < 8; r++)
#pragma unroll
        for (int c = 0; c < 4; c++) acc[r][c] = 0.f;

#pragma unroll 8
    for (int k = 0; k < 64; k++) {
        float4 b = *(float4*)&Ws[k * 128 + c0];
#pragma unroll
        for (int r = 0; r < 8; r++) {
            float a = As[(r0 + r) * 64 + k];
            acc[r][0] = fmaf(a, b.x, acc[r][0]);
            acc[r][1] = fmaf(a, b.y, acc[r][1]);
            acc[r][2] = fmaf(a, b.z, acc[r][2]);
            acc[r][3] = fmaf(a, b.w, acc[r][3]);
        }
    }

    float4 bias = *(const float4*)&b1[c0];
#pragma unroll
    for (int r = 0; r < 8; r++) {
        int row = base + r0 + r;
        if (row < n) {
            float4 o;
            o.x = acc[r][0] + bias.x;
            o.y = acc[r][1] + bias.y;
            o.z = acc[r][2] + bias.z;
            o.w = acc[r][3] + bias.w;
            o.x = (o.x > 0.f) ? o.x : expm1f(o.x);
            o.y = (o.y > 0.f) ? o.y : expm1f(o.y);
            o.z = (o.z > 0.f) ? o.z : expm1f(o.z);
            o.w = (o.w > 0.f) ? o.w : expm1f(o.w);
            *(float4*)(g_h + (size_t)row * 128 + c0) = o;
        }
    }
}

// -------- agg2 + mean-pool accumulate: pooled[g] += (A h)[i] ------------------
__global__ void agg2_pool_kernel(const int* __restrict__ batch, int n) {
    int warp = (blockIdx.x * blockDim.x + threadIdx.x) >> 5;
    int lane = threadIdx.x & 31;
    if (warp >= n) return;
    int i = warp;
    int p0 = g_rowptr[i], p1 = g_rowptr[i + 1];
    float4 acc = make_float4(0.f, 0.f, 0.f, 0.f);
    for (int p = p0; p < p1; ++p) {
        int s = g_col[p];
        float w = g_dinv[s];
        float4 v = *(const float4*)(g_h + (size_t)s * 128 + lane * 4);
        acc.x = fmaf(w, v.x, acc.x);
        acc.y = fmaf(w, v.y, acc.y);
        acc.z = fmaf(w, v.z, acc.z);
        acc.w = fmaf(w, v.w, acc.w);
    }
    float di = g_dinv[i];
    float4 hi = *(const float4*)(g_h + (size_t)i * 128 + lane * 4);
    float4 r;
    r.x = di * acc.x + di * di * hi.x;
    r.y = di * acc.y + di * di * hi.y;
    r.z = di * acc.z + di * di * hi.z;
    r.w = di * acc.w + di * di * hi.w;
    int g = batch[i];
    float* pg = g_pooled + g * 128 + lane * 4;
    atomicAdd(pg + 0, r.x);
    atomicAdd(pg + 1, r.y);
    atomicAdd(pg + 2, r.z);
    atomicAdd(pg + 3, r.w);
    if (lane == 0) atomicAdd(&g_cnt[g], 1.0f);
}

// ---------------- epilogue: W2 + MLP + log_softmax (1 block per graph) --------
__global__ void __launch_bounds__(128) final_kernel(
    const float* __restrict__ stats,
    const float* __restrict__ W2, const float* __restrict__ b2,
    const float* __restrict__ Wf1, const float* __restrict__ bf1,
    const float* __restrict__ Wf2, const float* __restrict__ bf2,
    float* __restrict__ out) {
    __shared__ float pm[128];
    __shared__ float zin[138];
    __shared__ float z1[20];
    __shared__ float z2[5];
    int g = blockIdx.x, t = threadIdx.x;
    float c = fmaxf(g_cnt[g], 1.0f);
    pm[t] = g_pooled[g * 128 + t] / c;
    __syncthreads();
    // pooled_mean @ W2 + b2
    float acc = b2[t];
#pragma unroll 8
    for (int k = 0; k < 128; k++) acc = fmaf(pm[k], W2[k * 128 + t], acc);
    zin[t] = acc;
    if (t < 10) zin[128 + t] = stats[g * 10 + t];
    __syncthreads();
    if (t < 20) {
        float a = bf1[t];
        for (int k = 0; k < 138; k++) a = fmaf(zin[k], Wf1[k * 20 + t], a);
        z1[t] = fmaxf(a, 0.0f);
    }
    __syncthreads();
    if (t < 5) {
        float a = bf2[t];
        for (int k = 0; k < 20; k++) a = fmaf(z1[k], Wf2[k * 5 + t], a);
        z2[t] = a;
    }
    __syncthreads();
    if (t == 0) {
        float m = z2[0];
        for (int i = 1; i < 5; i++) m = fmaxf(m, z2[i]);
        float sum = 0.0f;
        for (int i = 0; i < 5; i++) sum += expf(z2[i] - m);
        float ls = m + logf(sum);
        for (int i = 0; i < 5; i++) out[g * 5 + i] = z2[i] - ls;
    }
}

// ---------------------------------------------------------------------------
extern "C" void kernel_launch(void* const* d_in, const int* in_sizes, int n_in,
                              void* d_out, int out_size) {
    const float* x     = (const float*)d_in[0];
    const int*   ei    = (const int*)d_in[1];
    const int*   batch = (const int*)d_in[2];
    // d_in[3] = eig (unused by reference)
    const float* stats = (const float*)d_in[4];
    const float* W1    = (const float*)d_in[5];
    const float* b1    = (const float*)d_in[6];
    const float* W2    = (const float*)d_in[7];
    const float* b2    = (const float*)d_in[8];
    const float* Wf1   = (const float*)d_in[9];
    const float* bf1   = (const float*)d_in[10];
    const float* Wf2   = (const float*)d_in[11];
    const float* bf2   = (const float*)d_in[12];

    int n = in_sizes[0] / 64;
    int e = in_sizes[1] / 2;
    int G = in_sizes[4] / 10;

    init_kernel<<<(n + 255) / 256, 256>>>(n, G);
    count_kernel<<<(e + 255) / 256, 256>>>(ei, e);
    scan_kernel<<<1, 1024>>>(n);
    dinv_cursor_kernel<<<(n + 255) / 256, 256>>>(n);
    scatter_kernel<<<(e + 255) / 256, 256>>>(ei, e);
    agg1_kernel<<<(n * 32 + 255) / 256, 256>>>(x, n);
    gemm1_kernel<<<(n + 63) / 64, 256>>>(W1, b1, n);
    agg2_pool_kernel<<<(n * 32 + 255) / 256, 256>>>(batch, n);
    final_kernel<<<G, 128>>>(stats, W2, b2, Wf1, bf1, Wf2, bf2, (float*)d_out);
}

// round 4
// speedup vs baseline: 2.5525x; 2.5525x over previous
#include <cuda_runtime.h>
#include <math.h>

// ---------------------------------------------------------------------------
// GCN forward, restructured:
//   t1 = A x               (aggregate 64-dim, CSR)
//   h  = elu(t1 @ W1 + b1) (GEMM 100k x 64 x 128, packed f32x2 FFMA)
//   pooled_g += (A h)_i    (fused agg2 + mean-pool, shared-mem accumulation)
//   pooled_mean @ W2 -> concat stats -> MLP -> log_softmax (1 tiny kernel)
// A = D^-1/2 (Adj+I) D^-1/2 applied as dinv[i]*(sum dinv[s] v_s) + dinv[i]^2 v_i
// Integer inputs (edge_index, batch) arrive as int32.
// ---------------------------------------------------------------------------

#define MAXN 100000
#define MAXE 1600000
#define MAXG 64
#define MAXB ((MAXN + 4095) / 4096)

__device__ int   g_indeg[MAXN];
__device__ int   g_rowptr[MAXN + 1];
__device__ int   g_cursor[MAXN];
__device__ int   g_col[MAXE];
__device__ int   g_bsum[MAXB + 1];
__device__ int   g_cnti[MAXG];
__device__ float g_dinv[MAXN];
__device__ __align__(16) float g_t1[(size_t)MAXN * 64];
__device__ __align__(16) float g_h[(size_t)MAXN * 128];
__device__ float g_pooled[MAXG * 128];

// ---------------- init scratch (runs every replay) ---------------------------
__global__ void init_kernel(int n, int g) {
    int i = blockIdx.x * blockDim.x + threadIdx.x;
    if (i < n) g_indeg[i] = 0;
    if (i < g * 128) g_pooled[i] = 0.0f;
    if (i < g) g_cnti[i] = 0;
}

// ---------------- count in-degree (real edges only) --------------------------
__global__ void count_kernel(const int* __restrict__ ei, int e) {
    int idx = blockIdx.x * blockDim.x + threadIdx.x;
    if (idx < e) atomicAdd(&g_indeg[idx[ei + e]], 1);
}

// ---------------- scan phase 1: per-block (4096 elems) exclusive scan --------
__global__ void __launch_bounds__(256) scan1_kernel(int n) {
    __shared__ int sh[4096];
    __shared__ int wsum[8];
    int t = threadIdx.x;
    int base = blockIdx.x * 4096;
#pragma unroll
    for (int j = 0; j < 16; j++) {
        int idx = base + t + j * 256;
        sh[t + j * 256] = (idx < n) ? g_indeg[idx] : 0;
    }
    __syncthreads();
    int v[16];
    int run = 0;
#pragma unroll
    for (int j = 0; j < 16; j++) { v[j] = run; run += sh[t * 16 + j]; }
    int lane = t & 31, w = t >> 5;
    int incl = run;
#pragma unroll
    for (int off = 1; off < 32; off <<= 1) {
        int tmp = __shfl_up_sync(0xffffffffu, incl, off);
        if (lane >= off) incl += tmp;
    }
    if (lane == 31) wsum[w] = incl;
    __syncthreads();
    if (t == 0) {
        int s = 0;
#pragma unroll
        for (int k = 0; k < 8; k++) { int x = wsum[k]; wsum[k] = s; s += x; }
        g_bsum[blockIdx.x] = s;
    }
    __syncthreads();
    int texcl = wsum[w] + incl - run;
#pragma unroll
    for (int j = 0; j < 16; j++) sh[t * 16 + j] = texcl + v[j];
    __syncthreads();
#pragma unroll
    for (int j = 0; j < 16; j++) {
        int idx = base + t + j * 256;
        if (idx < n) g_rowptr[idx] = sh[t + j * 256];
    }
}

// ---------------- scan phase 2: scan block sums (1 warp) ----------------------
__global__ void scan2_kernel(int nb, int n) {
    int lane = threadIdx.x;
    int carry = 0;
    for (int base = 0; base < nb; base += 32) {
        int idx = base + lane;
        int x = (idx < nb) ? g_bsum[idx] : 0;
        int incl = x;
#pragma unroll
        for (int off = 1; off < 32; off <<= 1) {
            int tmp = __shfl_up_sync(0xffffffffu, incl, off);
            if (lane >= off) incl += tmp;
        }
        int excl = carry + incl - x;
        if (idx < nb) g_bsum[idx] = excl;
        carry += __shfl_sync(0xffffffffu, incl, 31);
    }
    if (lane == 0) g_rowptr[n] = carry;
}

// -------- scan phase 3: add block offsets + dinv + cursor + graph counts ------
__global__ void scan3_kernel(const int* __restrict__ batch, int n) {
    int i = blockIdx.x * blockDim.x + threadIdx.x;
    if (i < n) {
        int r = g_rowptr[i] + g_bsum[i >> 12];
        g_rowptr[i] = r;
        g_cursor[i] = r;
        g_dinv[i] = rsqrtf((float)(g_indeg[i] + 1));
        atomicAdd(&g_cnti[batch[i]], 1);
    }
}

// ---------------- scatter edges into CSR --------------------------------------
__global__ void scatter_kernel(const int* __restrict__ ei, int e) {
    int idx = blockIdx.x * blockDim.x + threadIdx.x;
    if (idx < e) {
        int s = ei[idx];
        int d = ei[e + idx];
        int pos = atomicAdd(&g_cursor[d], 1);
        g_col[pos] = s;
    }
}

// ---------------- agg1: t1 = A x  (64 feats, warp per node, unroll 4) ---------
__global__ void agg1_kernel(const float* __restrict__ x, int n) {
    int warp = (blockIdx.x * blockDim.x + threadIdx.x) >> 5;
    int lane = threadIdx.x & 31;
    if (warp >= n) return;
    int i = warp;
    int p0 = g_rowptr[i], p1 = g_rowptr[i + 1];
    float2 acc = make_float2(0.f, 0.f);
    int p = p0;
    for (; p + 4 <= p1; p += 4) {
        int s0 = g_col[p], s1 = g_col[p + 1], s2 = g_col[p + 2], s3 = g_col[p + 3];
        float w0 = g_dinv[s0], w1 = g_dinv[s1], w2 = g_dinv[s2], w3 = g_dinv[s3];
        float2 v0 = *(const float2*)(x + (size_t)s0 * 64 + lane * 2);
        float2 v1 = *(const float2*)(x + (size_t)s1 * 64 + lane * 2);
        float2 v2 = *(const float2*)(x + (size_t)s2 * 64 + lane * 2);
        float2 v3 = *(const float2*)(x + (size_t)s3 * 64 + lane * 2);
        acc.x = fmaf(w0, v0.x, acc.x); acc.y = fmaf(w0, v0.y, acc.y);
        acc.x = fmaf(w1, v1.x, acc.x); acc.y = fmaf(w1, v1.y, acc.y);
        acc.x = fmaf(w2, v2.x, acc.x); acc.y = fmaf(w2, v2.y, acc.y);
        acc.x = fmaf(w3, v3.x, acc.x); acc.y = fmaf(w3, v3.y, acc.y);
    }
    for (; p < p1; ++p) {
        int s = g_col[p];
        float w = g_dinv[s];
        float2 v = *(const float2*)(x + (size_t)s * 64 + lane * 2);
        acc.x = fmaf(w, v.x, acc.x); acc.y = fmaf(w, v.y, acc.y);
    }
    float di = g_dinv[i];
    float2 xi = *(const float2*)(x + (size_t)i * 64 + lane * 2);
    float2 r;
    r.x = di * acc.x + di * di * xi.x;
    r.y = di * acc.y + di * di * xi.y;
    *(float2*)(g_t1 + (size_t)i * 64 + lane * 2) = r;
}

// ---------------- GEMM: h = elu(t1 @ W1 + b1), packed f32x2 FFMA --------------
__global__ void __launch_bounds__(256) gemm1_kernel(const float* __restrict__ W1,
                                                    const float* __restrict__ b1,
                                                    int n) {
    __shared__ float As[64 * 64];
    __shared__ float Ws[64 * 128];
    int tid = threadIdx.x;
    int base = blockIdx.x * 64;

    const float4* Wv = (const float4*)W1;
    float4* Wsv = (float4*)Ws;
#pragma unroll
    for (int i = 0; i < 8; i++) Wsv[tid + i * 256] = Wv[tid + i * 256];

    const float4* Av = (const float4*)(g_t1 + (size_t)base * 64);
    float4* Asv = (float4*)As;
#pragma unroll
    for (int i = 0; i < 4; i++) {
        int idx = tid + i * 256;
        int row = base + (idx >> 4);
        float4 v = (row < n) ? Av[idx] : make_float4(0.f, 0.f, 0.f, 0.f);
        Asv[idx] = v;
    }
    __syncthreads();

    int tx = tid & 31, ty = tid >> 5;
    int c0 = tx * 4, r0 = ty * 8;
    unsigned long long accp[8][2];
#pragma unroll
    for (int r = 0; r < 8; r++) { accp[r][0] = 0ull; accp[r][1] = 0ull; }

#pragma unroll 4
    for (int k = 0; k < 64; k++) {
        ulonglong2 bb = *(const ulonglong2*)(Ws + k * 128 + c0);
#pragma unroll
        for (int r = 0; r < 8; r++) {
            unsigned int au = __float_as_uint(As[(r0 + r) * 64 + k]);
            unsigned long long ap;
            asm("mov.b64 %0, {%1, %1};" : "=l"(ap) : "r"(au));
            asm("fma.rn.f32x2 %0, %1, %2, %0;" : "+l"(accp[r][0]) : "l"(ap), "l"(bb.x));
            asm("fma.rn.f32x2 %0, %1, %2, %0;" : "+l"(accp[r][1]) : "l"(ap), "l"(bb.y));
        }
    }

    float4 bias = *(const float4*)&b1[c0];
#pragma unroll
    for (int r = 0; r < 8; r++) {
        int row = base + r0 + r;
        if (row < n) {
            unsigned int u0, u1, u2, u3;
            asm("mov.b64 {%0, %1}, %2;" : "=r"(u0), "=r"(u1) : "l"(accp[r][0]));
            asm("mov.b64 {%0, %1}, %2;" : "=r"(u2), "=r"(u3) : "l"(accp[r][1]));
            float4 o;
            o.x = __uint_as_float(u0) + bias.x;
            o.y = __uint_as_float(u1) + bias.y;
            o.z = __uint_as_float(u2) + bias.z;
            o.w = __uint_as_float(u3) + bias.w;
            o.x = (o.x > 0.f) ? o.x : expm1f(o.x);
            o.y = (o.y > 0.f) ? o.y : expm1f(o.y);
            o.z = (o.z > 0.f) ? o.z : expm1f(o.z);
            o.w = (o.w > 0.f) ? o.w : expm1f(o.w);
            *(float4*)(g_h + (size_t)row * 128 + c0) = o;
        }
    }
}

// -------- agg2 + mean-pool: pooled[g] += (A h)_i, shared-mem staging ----------
__global__ void __launch_bounds__(256) agg2_pool_kernel(const int* __restrict__ batch, int n) {
    __shared__ float ps[128];
    __shared__ int g0_s;
    int tid = threadIdx.x;
    int lane = tid & 31;
    int wid = tid >> 5;
    int node0 = blockIdx.x * 8;
    if (tid < 128) ps[tid] = 0.0f;
    if (tid == 0) g0_s = batch[node0 < n ? node0 : (n - 1)];
    __syncthreads();
    int g0 = g0_s;

    int i = node0 + wid;
    if (i < n) {
        int p0 = g_rowptr[i], p1 = g_rowptr[i + 1];
        float4 acc = make_float4(0.f, 0.f, 0.f, 0.f);
        int p = p0;
        for (; p + 4 <= p1; p += 4) {
            int s0 = g_col[p], s1 = g_col[p + 1], s2 = g_col[p + 2], s3 = g_col[p + 3];
            float w0 = g_dinv[s0], w1 = g_dinv[s1], w2 = g_dinv[s2], w3 = g_dinv[s3];
            float4 v0 = *(const float4*)(g_h + (size_t)s0 * 128 + lane * 4);
            float4 v1 = *(const float4*)(g_h + (size_t)s1 * 128 + lane * 4);
            float4 v2 = *(const float4*)(g_h + (size_t)s2 * 128 + lane * 4);
            float4 v3 = *(const float4*)(g_h + (size_t)s3 * 128 + lane * 4);
            acc.x = fmaf(w0, v0.x, acc.x); acc.y = fmaf(w0, v0.y, acc.y);
            acc.z = fmaf(w0, v0.z, acc.z); acc.w = fmaf(w0, v0.w, acc.w);
            acc.x = fmaf(w1, v1.x, acc.x); acc.y = fmaf(w1, v1.y, acc.y);
            acc.z = fmaf(w1, v1.z, acc.z); acc.w = fmaf(w1, v1.w, acc.w);
            acc.x = fmaf(w2, v2.x, acc.x); acc.y = fmaf(w2, v2.y, acc.y);
            acc.z = fmaf(w2, v2.z, acc.z); acc.w = fmaf(w2, v2.w, acc.w);
            acc.x = fmaf(w3, v3.x, acc.x); acc.y = fmaf(w3, v3.y, acc.y);
            acc.z = fmaf(w3, v3.z, acc.z); acc.w = fmaf(w3, v3.w, acc.w);
        }
        for (; p < p1; ++p) {
            int s = g_col[p];
            float w = g_dinv[s];
            float4 v = *(const float4*)(g_h + (size_t)s * 128 + lane * 4);
            acc.x = fmaf(w, v.x, acc.x); acc.y = fmaf(w, v.y, acc.y);
            acc.z = fmaf(w, v.z, acc.z); acc.w = fmaf(w, v.w, acc.w);
        }
        float di = g_dinv[i];
        float4 hi = *(const float4*)(g_h + (size_t)i * 128 + lane * 4);
        float4 r;
        r.x = di * acc.x + di * di * hi.x;
        r.y = di * acc.y + di * di * hi.y;
        r.z = di * acc.z + di * di * hi.z;
        r.w = di * acc.w + di * di * hi.w;
        int g = batch[i];
        if (g == g0) {
            atomicAdd(&ps[lane * 4 + 0], r.x);
            atomicAdd(&ps[lane * 4 + 1], r.y);
            atomicAdd(&ps[lane * 4 + 2], r.z);
            atomicAdd(&ps[lane * 4 + 3], r.w);
        } else {
            float* pg = g_pooled + g * 128 + lane * 4;
            atomicAdd(pg + 0, r.x);
            atomicAdd(pg + 1, r.y);
            atomicAdd(pg + 2, r.z);
            atomicAdd(pg + 3, r.w);
        }
    }
    __syncthreads();
    if (tid < 128) atomicAdd(&g_pooled[g0 * 128 + tid], ps[tid]);
}

// ---------------- epilogue: W2 + MLP + log_softmax (1 block per graph) --------
__global__ void __launch_bounds__(128) final_kernel(
    const float* __restrict__ stats,
    const float* __restrict__ W2, const float* __restrict__ b2,
    const float* __restrict__ Wf1, const float* __restrict__ bf1,
    const float* __restrict__ Wf2, const float* __restrict__ bf2,
    float* __restrict__ out) {
    __shared__ float pm[128];
    __shared__ float zin[138];
    __shared__ float z1[20];
    __shared__ float z2[5];
    int g = blockIdx.x, t = threadIdx.x;
    float c = fmaxf((float)g_cnti[g], 1.0f);
    pm[t] = g_pooled[g * 128 + t] / c;
    __syncthreads();
    float acc = b2[t];
#pragma unroll 8
    for (int k = 0; k < 128; k++) acc = fmaf(pm[k], W2[k * 128 + t], acc);
    zin[t] = acc;
    if (t < 10) zin[128 + t] = stats[g * 10 + t];
    __syncthreads();
    if (t < 20) {
        float a = bf1[t];
        for (int k = 0; k < 138; k++) a = fmaf(zin[k], Wf1[k * 20 + t], a);
        z1[t] = fmaxf(a, 0.0f);
    }
    __syncthreads();
    if (t < 5) {
        float a = bf2[t];
        for (int k = 0; k < 20; k++) a = fmaf(z1[k], Wf2[k * 5 + t], a);
        z2[t] = a;
    }
    __syncthreads();
    if (t == 0) {
        float m = z2[0];
        for (int i = 1; i < 5; i++) m = fmaxf(m, z2[i]);
        float sum = 0.0f;
        for (int i = 0; i < 5; i++) sum += expf(z2[i] - m);
        float ls = m + logf(sum);
        for (int i = 0; i < 5; i++) out[g * 5 + i] = z2[i] - ls;
    }
}

// ---------------------------------------------------------------------------
extern "C" void kernel_launch(void* const* d_in, const int* in_sizes, int n_in,
                              void* d_out, int out_size) {
    const float* x     = (const float*)d_in[0];
    const int*   ei    = (const int*)d_in[1];
    const int*   batch = (const int*)d_in[2];
    const float* stats = (const float*)d_in[4];
    const float* W1    = (const float*)d_in[5];
    const float* b1    = (const float*)d_in[6];
    const float* W2    = (const float*)d_in[7];
    const float* b2    = (const float*)d_in[8];
    const float* Wf1   = (const float*)d_in[9];
    const float* bf1   = (const float*)d_in[10];
    const float* Wf2   = (const float*)d_in[11];
    const float* bf2   = (const float*)d_in[12];

    int n = in_sizes[0] / 64;
    int e = in_sizes[1] / 2;
    int G = in_sizes[4] / 10;
    int nb = (n + 4095) / 4096;

    init_kernel<<<(n + 255) / 256, 256>>>(n, G);
    count_kernel<<<(e + 255) / 256, 256>>>(ei, e);
    scan1_kernel<<<nb, 256>>>(n);
    scan2_kernel<<<1, 32>>>(nb, n);
    scan3_kernel<<<(n + 255) / 256, 256>>>(batch, n);
    scatter_kernel<<<(e + 255) / 256, 256>>>(ei, e);
    agg1_kernel<<<(n * 32 + 255) / 256, 256>>>(x, n);
    gemm1_kernel<<<(n + 63) / 64, 256>>>(W1, b1, n);
    agg2_pool_kernel<<<(n + 7) / 8, 256>>>(batch, n);
    final_kernel<<<G, 128>>>(stats, W2, b2, Wf1, bf1, Wf2, bf2, (float*)d_out);
}